// round 1
// baseline (speedup 1.0000x reference)
#include <cuda_runtime.h>
#include <math.h>

#define BATCH 4096
#define DIM   1024
#define EPS_W 0.05f
#define REG_W 0.1f
#define NITER 10
#define INV_B (1.0f/4096.0f)

// ---------------- scratch (static device globals; no allocation) ----------------
__device__ float g_an[(size_t)BATCH * DIM];          // 16 MB normalized audio
__device__ float g_tn[(size_t)BATCH * DIM];          // 16 MB normalized text
__device__ float g_K[(size_t)BATCH * BATCH];         // 64 MB: M, then K in place
__device__ float g_part[128 * BATCH];                // 2 MB column partials
__device__ float g_u[BATCH];
__device__ float g_v[BATCH];
__device__ float g_col[BATCH];
__device__ float g_ce[BATCH];                        // per-row (lse - pi_ii)
__device__ float g_rowsum[BATCH];
__device__ unsigned int g_maxbits;

// ---------------- helpers ----------------
__device__ __forceinline__ float blockReduceSum(float v, float* sh) {
    __syncthreads();                 // safe reuse of sh across calls
    int lane = threadIdx.x & 31;
    int w    = threadIdx.x >> 5;
    #pragma unroll
    for (int o = 16; o > 0; o >>= 1) v += __shfl_down_sync(0xffffffffu, v, o);
    if (lane == 0) sh[w] = v;
    __syncthreads();
    int nw = blockDim.x >> 5;
    v = (threadIdx.x < nw) ? sh[threadIdx.x] : 0.0f;
    if (w == 0) {
        #pragma unroll
        for (int o = 16; o > 0; o >>= 1) v += __shfl_down_sync(0xffffffffu, v, o);
    }
    if (threadIdx.x == 0) sh[0] = v;
    __syncthreads();
    return sh[0];
}

// ---------------- kernels ----------------

__global__ void init_kernel() {
    int i = blockIdx.x * 256 + threadIdx.x;
    if (i < BATCH) g_u[i] = INV_B;
    if (i == 0) g_maxbits = 0u;
}

// row-normalize both embedding matrices (block per row; 1024 floats = 256 float4)
__global__ void normalize_kernel(const float* __restrict__ audio,
                                 const float* __restrict__ text) {
    __shared__ float sh[8];
    int row = blockIdx.x;
    const float* src;
    float* dst;
    if (row < BATCH) { src = audio + (size_t)row * DIM;           dst = g_an + (size_t)row * DIM; }
    else             { src = text  + (size_t)(row - BATCH) * DIM; dst = g_tn + (size_t)(row - BATCH) * DIM; }
    float4 v = ((const float4*)src)[threadIdx.x];
    float ss = v.x*v.x + v.y*v.y + v.z*v.z + v.w*v.w;
    float tot = blockReduceSum(ss, sh);
    float inv = 1.0f / sqrtf(tot);
    v.x *= inv; v.y *= inv; v.z *= inv; v.w *= inv;
    ((float4*)dst)[threadIdx.x] = v;
}

// C = an @ tn^T ; writes M = 1 - C into g_K and tracks global max(M) (all M >= 0)
__global__ void __launch_bounds__(256) gemm_kernel() {
    __shared__ float As[16][128 + 4];
    __shared__ float Bs[16][128 + 4];
    __shared__ float shmax[256];

    int tid = threadIdx.x;
    int tx = tid & 15;           // 0..15  -> 8 cols each
    int ty = tid >> 4;           // 0..15  -> 8 rows each
    int row0 = blockIdx.y * 128;
    int col0 = blockIdx.x * 128;

    float acc[8][8];
    #pragma unroll
    for (int i = 0; i < 8; i++)
        #pragma unroll
        for (int j = 0; j < 8; j++) acc[i][j] = 0.0f;

    for (int k0 = 0; k0 < DIM; k0 += 16) {
        // load A tile (128 rows x 16 k) : 512 float4, 2 per thread
        #pragma unroll
        for (int l = 0; l < 2; l++) {
            int idx = tid + l * 256;       // 0..511
            int r  = idx >> 2;             // 0..127
            int kq = (idx & 3) * 4;        // 0,4,8,12
            float4 va = *(const float4*)&g_an[(size_t)(row0 + r) * DIM + k0 + kq];
            As[kq + 0][r] = va.x; As[kq + 1][r] = va.y;
            As[kq + 2][r] = va.z; As[kq + 3][r] = va.w;
            float4 vb = *(const float4*)&g_tn[(size_t)(col0 + r) * DIM + k0 + kq];
            Bs[kq + 0][r] = vb.x; Bs[kq + 1][r] = vb.y;
            Bs[kq + 2][r] = vb.z; Bs[kq + 3][r] = vb.w;
        }
        __syncthreads();

        #pragma unroll
        for (int kk = 0; kk < 16; kk++) {
            float4 a0 = *(const float4*)&As[kk][ty * 8];
            float4 a1 = *(const float4*)&As[kk][ty * 8 + 4];
            float4 b0 = *(const float4*)&Bs[kk][tx * 8];
            float4 b1 = *(const float4*)&Bs[kk][tx * 8 + 4];
            float ra[8] = {a0.x,a0.y,a0.z,a0.w,a1.x,a1.y,a1.z,a1.w};
            float rb[8] = {b0.x,b0.y,b0.z,b0.w,b1.x,b1.y,b1.z,b1.w};
            #pragma unroll
            for (int i = 0; i < 8; i++)
                #pragma unroll
                for (int j = 0; j < 8; j++) acc[i][j] += ra[i] * rb[j];
        }
        __syncthreads();
    }

    // epilogue: M = 1 - C, store, track max
    float bmax = 0.0f;
    #pragma unroll
    for (int i = 0; i < 8; i++) {
        float m[8];
        #pragma unroll
        for (int j = 0; j < 8; j++) {
            m[j] = 1.0f - acc[i][j];
            bmax = fmaxf(bmax, m[j]);
        }
        float* out = &g_K[(size_t)(row0 + ty * 8 + i) * BATCH + col0 + tx * 8];
        ((float4*)out)[0] = make_float4(m[0], m[1], m[2], m[3]);
        ((float4*)out)[1] = make_float4(m[4], m[5], m[6], m[7]);
    }
    shmax[tid] = bmax;
    __syncthreads();
    for (int s = 128; s > 0; s >>= 1) {
        if (tid < s) shmax[tid] = fmaxf(shmax[tid], shmax[tid + s]);
        __syncthreads();
    }
    if (tid == 0) atomicMax(&g_maxbits, __float_as_uint(shmax[0]));
}

// K = exp(-M / (eps * maxM)) in place (16 M elems, float4 per thread)
__global__ void expk_kernel() {
    size_t i = (size_t)blockIdx.x * 256 + threadIdx.x;   // 0 .. 4194303
    float mx = __uint_as_float(g_maxbits);
    float s = -1.0f / (EPS_W * mx);
    float4 m = ((const float4*)g_K)[i];
    m.x = expf(m.x * s); m.y = expf(m.y * s);
    m.z = expf(m.z * s); m.w = expf(m.w * s);
    ((float4*)g_K)[i] = m;
}

// stage 1 of column reduction: partial of sum_i u_i * K[i][j] (optionally * v_j)
// 128 blocks x 256 threads; block handles a 32-row stripe; thread owns 16 columns
template<bool WITHV>
__global__ void colpart_kernel() {
    int t   = threadIdx.x;       // 256
    int blk = blockIdx.x;        // 128
    int r0  = blk * 32;
    float4 acc[4];
    #pragma unroll
    for (int k = 0; k < 4; k++) acc[k] = make_float4(0.f, 0.f, 0.f, 0.f);

    for (int r = 0; r < 32; r++) {
        float ur = g_u[r0 + r];
        const float4* Krow = (const float4*)(g_K + (size_t)(r0 + r) * BATCH);
        #pragma unroll
        for (int k = 0; k < 4; k++) {
            float4 kv = Krow[t + 256 * k];
            acc[k].x += ur * kv.x; acc[k].y += ur * kv.y;
            acc[k].z += ur * kv.z; acc[k].w += ur * kv.w;
        }
    }
    float4* out = (float4*)(g_part + (size_t)blk * BATCH);
    #pragma unroll
    for (int k = 0; k < 4; k++) {
        if (WITHV) {
            float4 vv = ((const float4*)g_v)[t + 256 * k];
            acc[k].x *= vv.x; acc[k].y *= vv.y; acc[k].z *= vv.z; acc[k].w *= vv.w;
        }
        out[t + 256 * k] = acc[k];
    }
}

// stage 2: reduce the 128 partials. mode 0: v_j = (1/B)/s ; mode 1: col_j = s
__global__ void colreduce_kernel(int mode) {
    int c = blockIdx.x * 256 + threadIdx.x;   // grid 16
    float s = 0.0f;
    #pragma unroll 8
    for (int b = 0; b < 128; b++) s += g_part[(size_t)b * BATCH + c];
    if (mode == 0) g_v[c] = INV_B / s;
    else           g_col[c] = s;
}

// u_r = (1/B) / (K v)_r  (block per row, 128 threads, float4)
__global__ void rowdot_kernel() {
    __shared__ float sh[4];
    int r = blockIdx.x;
    int t = threadIdx.x;    // 128
    const float4* Krow = (const float4*)(g_K + (size_t)r * BATCH);
    const float4* vv = (const float4*)g_v;
    float s = 0.0f;
    #pragma unroll
    for (int i = 0; i < 8; i++) {
        float4 k4 = Krow[t + 128 * i];
        float4 v4 = vv[t + 128 * i];
        s += k4.x*v4.x + k4.y*v4.y + k4.z*v4.z + k4.w*v4.w;
    }
    float tot = blockReduceSum(s, sh);
    if (t == 0) g_u[r] = INV_B / tot;
}

// per-row: pi = u_r * K[r][:] * v ; compute logsumexp(exp(pi)) (pi tiny -> no shift
// needed), rowsum, and diag term.  ce term = lse - pi_rr
__global__ void rowfinal_kernel() {
    __shared__ float sh[4];
    int r = blockIdx.x;
    int t = threadIdx.x;    // 128
    float ur = g_u[r];
    const float4* Krow = (const float4*)(g_K + (size_t)r * BATCH);
    const float4* vv = (const float4*)g_v;
    float se = 0.0f, rs = 0.0f;
    #pragma unroll
    for (int i = 0; i < 8; i++) {
        float4 k4 = Krow[t + 128 * i];
        float4 v4 = vv[t + 128 * i];
        float p0 = ur * k4.x * v4.x;
        float p1 = ur * k4.y * v4.y;
        float p2 = ur * k4.z * v4.z;
        float p3 = ur * k4.w * v4.w;
        se += expf(p0) + expf(p1) + expf(p2) + expf(p3);
        rs += p0 + p1 + p2 + p3;
    }
    float se_t = blockReduceSum(se, sh);
    float rs_t = blockReduceSum(rs, sh);
    if (t == 0) {
        float diag = ur * g_K[(size_t)r * BATCH + r] * g_v[r];
        g_ce[r] = logf(se_t) - diag;
        g_rowsum[r] = rs_t;
    }
}

// combine everything into the scalar loss
__global__ void final_kernel(float* __restrict__ out) {
    __shared__ float sh[8];
    int t = threadIdx.x;   // 256
    float ce = 0.0f, klr = 0.0f, klc = 0.0f;
    for (int i = t; i < BATCH; i += 256) {
        ce += g_ce[i];
        float rs = g_rowsum[i];
        klr += rs * (logf(rs) - INV_B);
        float cs = g_col[i];
        klc += cs * (logf(cs) - INV_B);
    }
    float ce_t  = blockReduceSum(ce,  sh);
    float klr_t = blockReduceSum(klr, sh);
    float klc_t = blockReduceSum(klc, sh);
    if (t == 0)
        out[0] = ce_t * INV_B + REG_W * (klc_t * INV_B + klr_t * INV_B);
}

// ---------------- launcher ----------------
extern "C" void kernel_launch(void* const* d_in, const int* in_sizes, int n_in,
                              void* d_out, int out_size) {
    const float* audio = (const float*)d_in[0];
    const float* text  = (const float*)d_in[1];
    // d_in[2] = labels (unused by the reference computation)
    float* out = (float*)d_out;

    init_kernel<<<16, 256>>>();
    normalize_kernel<<<2 * BATCH, 256>>>(audio, text);
    gemm_kernel<<<dim3(32, 32), 256>>>();
    expk_kernel<<<16384, 256>>>();

    for (int it = 0; it < NITER; it++) {
        colpart_kernel<false><<<128, 256>>>();
        colreduce_kernel<<<16, 256>>>(0);
        rowdot_kernel<<<BATCH, 128>>>();
    }

    colpart_kernel<true><<<128, 256>>>();
    colreduce_kernel<<<16, 256>>>(1);
    rowfinal_kernel<<<BATCH, 128>>>();
    final_kernel<<<1, 256>>>(out);
}

// round 4
// speedup vs baseline: 3.9741x; 3.9741x over previous
#include <cuda_runtime.h>
#include <cuda_bf16.h>
#include <math.h>
#include <stdint.h>

#define BATCH 4096
#define DIM   1024
#define EPS_W 0.05f
#define REG_W 0.1f
#define NITER 10
#define INV_B (1.0f/4096.0f)

// GEMM tiling (mma.sync path — tcgen05 is 'a'-gated and this build targets plain sm_103)
#define BM 128
#define BN 128
#define BK 32
#define APAD 8
#define ASTRIDE (BK + APAD)     // 40 bf16 = 80 bytes, conflict-free for ldmatrix

// ---------------- scratch (static device globals; no allocation) ----------------
__device__ __nv_bfloat16 g_an[(size_t)BATCH * DIM];  // 8 MB normalized audio (bf16)
__device__ __nv_bfloat16 g_tn[(size_t)BATCH * DIM];  // 8 MB normalized text  (bf16)
__device__ float g_K[(size_t)BATCH * BATCH];         // 64 MB: M, then K in place
__device__ float g_part[128 * BATCH];                // 2 MB column partials
__device__ float g_u[BATCH];
__device__ float g_v[BATCH];
__device__ float g_col[BATCH];
__device__ float g_ce[BATCH];
__device__ float g_rowsum[BATCH];
__device__ unsigned int g_maxbits;

// ---------------- helpers ----------------
__device__ __forceinline__ uint32_t smem_u32(const void* p) {
    uint32_t a;
    asm("{ .reg .u64 t; cvta.to.shared.u64 t, %1; cvt.u32.u64 %0, t; }" : "=r"(a) : "l"(p));
    return a;
}

__device__ __forceinline__ void cp_async16(uint32_t dst, const void* src) {
    asm volatile("cp.async.cg.shared.global [%0], [%1], 16;" :: "r"(dst), "l"(src));
}
#define CP_COMMIT() asm volatile("cp.async.commit_group;" ::: "memory")
#define CP_WAIT(n)  asm volatile("cp.async.wait_group %0;" :: "n"(n) : "memory")

__device__ __forceinline__ void ldmatrix_x4(uint32_t& r0, uint32_t& r1, uint32_t& r2,
                                            uint32_t& r3, uint32_t addr) {
    asm volatile("ldmatrix.sync.aligned.m8n8.x4.shared.b16 {%0,%1,%2,%3}, [%4];"
                 : "=r"(r0), "=r"(r1), "=r"(r2), "=r"(r3) : "r"(addr));
}
__device__ __forceinline__ void ldmatrix_x2(uint32_t& r0, uint32_t& r1, uint32_t addr) {
    asm volatile("ldmatrix.sync.aligned.m8n8.x2.shared.b16 {%0,%1}, [%2];"
                 : "=r"(r0), "=r"(r1) : "r"(addr));
}
__device__ __forceinline__ void mma_bf16(float& c0, float& c1, float& c2, float& c3,
                                         uint32_t a0, uint32_t a1, uint32_t a2, uint32_t a3,
                                         uint32_t b0, uint32_t b1) {
    asm volatile("mma.sync.aligned.m16n8k16.row.col.f32.bf16.bf16.f32 "
                 "{%0,%1,%2,%3}, {%4,%5,%6,%7}, {%8,%9}, {%0,%1,%2,%3};"
                 : "+f"(c0), "+f"(c1), "+f"(c2), "+f"(c3)
                 : "r"(a0), "r"(a1), "r"(a2), "r"(a3), "r"(b0), "r"(b1));
}

__device__ __forceinline__ float blockReduceSum(float v, float* sh) {
    __syncthreads();
    int lane = threadIdx.x & 31;
    int w    = threadIdx.x >> 5;
    #pragma unroll
    for (int o = 16; o > 0; o >>= 1) v += __shfl_down_sync(0xffffffffu, v, o);
    if (lane == 0) sh[w] = v;
    __syncthreads();
    int nw = blockDim.x >> 5;
    v = (threadIdx.x < nw) ? sh[threadIdx.x] : 0.0f;
    if (w == 0) {
        #pragma unroll
        for (int o = 16; o > 0; o >>= 1) v += __shfl_down_sync(0xffffffffu, v, o);
    }
    if (threadIdx.x == 0) sh[0] = v;
    __syncthreads();
    return sh[0];
}

// ---------------- kernels ----------------

__global__ void init_kernel() {
    int i = blockIdx.x * 256 + threadIdx.x;
    if (i < BATCH) g_u[i] = INV_B;
    if (i == 0) g_maxbits = 0u;
}

// row-normalize; write bf16 outputs for the tensor-core GEMM
__global__ void normalize_kernel(const float* __restrict__ audio,
                                 const float* __restrict__ text) {
    __shared__ float sh[8];
    int row = blockIdx.x;
    const float* src;
    __nv_bfloat16* dst;
    if (row < BATCH) { src = audio + (size_t)row * DIM;           dst = g_an + (size_t)row * DIM; }
    else             { src = text  + (size_t)(row - BATCH) * DIM; dst = g_tn + (size_t)(row - BATCH) * DIM; }
    float4 v = ((const float4*)src)[threadIdx.x];
    float ss = v.x*v.x + v.y*v.y + v.z*v.z + v.w*v.w;
    float tot = blockReduceSum(ss, sh);
    float inv = rsqrtf(tot);
    __nv_bfloat162 h0 = __floats2bfloat162_rn(v.x * inv, v.y * inv);
    __nv_bfloat162 h1 = __floats2bfloat162_rn(v.z * inv, v.w * inv);
    ((__nv_bfloat162*)dst)[2 * threadIdx.x + 0] = h0;
    ((__nv_bfloat162*)dst)[2 * threadIdx.x + 1] = h1;
}

// mma.sync bf16 GEMM: M = 1 - an @ tn^T -> g_K (fp32), track global max.
// CTA 128x128, BK=32 double-buffered cp.async, 8 warps of 64x32.
__global__ void __launch_bounds__(256) gemm_mma_kernel() {
    __shared__ __nv_bfloat16 As[2][BM][ASTRIDE];
    __shared__ __nv_bfloat16 Bs[2][BN][ASTRIDE];
    __shared__ float sred[256];

    int t    = threadIdx.x;
    int wid  = t >> 5;
    int lane = t & 31;
    int warp_m = wid & 1;       // 2 warps in M: 64 rows each
    int warp_n = wid >> 1;      // 4 warps in N: 32 cols each
    int row0 = blockIdx.y * BM;
    int col0 = blockIdx.x * BN;

    // cp.async load indexing: 512 chunks of 16B per tile; 2 per thread
    int cid0 = t, cid1 = t + 256;
    int ar0 = cid0 >> 2, ak0 = (cid0 & 3) * 8;
    int ar1 = cid1 >> 2, ak1 = (cid1 & 3) * 8;

    float acc[4][4][4];
    #pragma unroll
    for (int i = 0; i < 4; i++)
        #pragma unroll
        for (int j = 0; j < 4; j++)
            #pragma unroll
            for (int r = 0; r < 4; r++) acc[i][j][r] = 0.0f;

    auto load_stage = [&](int buf, int k0) {
        cp_async16(smem_u32(&As[buf][ar0][ak0]), &g_an[(size_t)(row0 + ar0) * DIM + k0 + ak0]);
        cp_async16(smem_u32(&As[buf][ar1][ak1]), &g_an[(size_t)(row0 + ar1) * DIM + k0 + ak1]);
        cp_async16(smem_u32(&Bs[buf][ar0][ak0]), &g_tn[(size_t)(col0 + ar0) * DIM + k0 + ak0]);
        cp_async16(smem_u32(&Bs[buf][ar1][ak1]), &g_tn[(size_t)(col0 + ar1) * DIM + k0 + ak1]);
        CP_COMMIT();
    };

    load_stage(0, 0);

    const int NK = DIM / BK;   // 32
    for (int c = 0; c < NK; c++) {
        int buf = c & 1;
        if (c + 1 < NK) load_stage(buf ^ 1, (c + 1) * BK);
        if (c + 1 < NK) CP_WAIT(1); else CP_WAIT(0);
        __syncthreads();

        #pragma unroll
        for (int kk = 0; kk < BK; kk += 16) {
            uint32_t a[4][4], b[4][2];
            #pragma unroll
            for (int i = 0; i < 4; i++) {
                uint32_t addr = smem_u32(&As[buf][warp_m * 64 + i * 16 + (lane & 15)]
                                            [kk + (lane >> 4) * 8]);
                ldmatrix_x4(a[i][0], a[i][1], a[i][2], a[i][3], addr);
            }
            #pragma unroll
            for (int j = 0; j < 4; j++) {
                uint32_t addr = smem_u32(&Bs[buf][warp_n * 32 + j * 8 + (lane & 7)]
                                            [kk + ((lane >> 3) & 1) * 8]);
                ldmatrix_x2(b[j][0], b[j][1], addr);
            }
            #pragma unroll
            for (int i = 0; i < 4; i++)
                #pragma unroll
                for (int j = 0; j < 4; j++)
                    mma_bf16(acc[i][j][0], acc[i][j][1], acc[i][j][2], acc[i][j][3],
                             a[i][0], a[i][1], a[i][2], a[i][3], b[j][0], b[j][1]);
        }
        __syncthreads();
    }

    // epilogue: M = 1 - C, store, track max
    float bmax = 0.0f;
    int rr = lane >> 2;          // 0..7
    int cc = (lane & 3) * 2;     // 0,2,4,6
    #pragma unroll
    for (int i = 0; i < 4; i++) {
        #pragma unroll
        for (int j = 0; j < 4; j++) {
            float m0 = 1.0f - acc[i][j][0];
            float m1 = 1.0f - acc[i][j][1];
            float m2 = 1.0f - acc[i][j][2];
            float m3 = 1.0f - acc[i][j][3];
            bmax = fmaxf(bmax, fmaxf(fmaxf(m0, m1), fmaxf(m2, m3)));
            int row = row0 + warp_m * 64 + i * 16 + rr;
            int col = col0 + warp_n * 32 + j * 8 + cc;
            *(float2*)&g_K[(size_t)row * BATCH + col]       = make_float2(m0, m1);
            *(float2*)&g_K[(size_t)(row + 8) * BATCH + col] = make_float2(m2, m3);
        }
    }
    sred[t] = bmax;
    __syncthreads();
    for (int s = 128; s > 0; s >>= 1) {
        if (t < s) sred[t] = fmaxf(sred[t], sred[t + s]);
        __syncthreads();
    }
    if (t == 0) atomicMax(&g_maxbits, __float_as_uint(sred[0]));
}

// K = exp(-M / (eps * maxM)) in place
__global__ void expk_kernel() {
    size_t i = (size_t)blockIdx.x * 256 + threadIdx.x;
    float mx = __uint_as_float(g_maxbits);
    float s = -1.0f / (EPS_W * mx);
    float4 m = ((const float4*)g_K)[i];
    m.x = expf(m.x * s); m.y = expf(m.y * s);
    m.z = expf(m.z * s); m.w = expf(m.w * s);
    ((float4*)g_K)[i] = m;
}

// stage 1 column reduction: partials of sum_i u_i * K[i][j] (optionally * v_j)
template<bool WITHV>
__global__ void colpart_kernel() {
    int t   = threadIdx.x;       // 256
    int blk = blockIdx.x;        // 128
    int r0  = blk * 32;
    float4 acc[4];
    #pragma unroll
    for (int k = 0; k < 4; k++) acc[k] = make_float4(0.f, 0.f, 0.f, 0.f);

    for (int r = 0; r < 32; r++) {
        float ur = g_u[r0 + r];
        const float4* Krow = (const float4*)(g_K + (size_t)(r0 + r) * BATCH);
        #pragma unroll
        for (int k = 0; k < 4; k++) {
            float4 kv = Krow[t + 256 * k];
            acc[k].x += ur * kv.x; acc[k].y += ur * kv.y;
            acc[k].z += ur * kv.z; acc[k].w += ur * kv.w;
        }
    }
    float4* out = (float4*)(g_part + (size_t)blk * BATCH);
    #pragma unroll
    for (int k = 0; k < 4; k++) {
        if (WITHV) {
            float4 vv = ((const float4*)g_v)[t + 256 * k];
            acc[k].x *= vv.x; acc[k].y *= vv.y; acc[k].z *= vv.z; acc[k].w *= vv.w;
        }
        out[t + 256 * k] = acc[k];
    }
}

// stage 2: reduce the 128 partials. mode 0: v_j = (1/B)/s ; mode 1: col_j = s
__global__ void colreduce_kernel(int mode) {
    int c = blockIdx.x * 256 + threadIdx.x;
    float s = 0.0f;
    #pragma unroll 8
    for (int b = 0; b < 128; b++) s += g_part[(size_t)b * BATCH + c];
    if (mode == 0) g_v[c] = INV_B / s;
    else           g_col[c] = s;
}

// u_r = (1/B) / (K v)_r
__global__ void rowdot_kernel() {
    __shared__ float sh[4];
    int r = blockIdx.x;
    int t = threadIdx.x;    // 128
    const float4* Krow = (const float4*)(g_K + (size_t)r * BATCH);
    const float4* vv = (const float4*)g_v;
    float s = 0.0f;
    #pragma unroll
    for (int i = 0; i < 8; i++) {
        float4 k4 = Krow[t + 128 * i];
        float4 v4 = vv[t + 128 * i];
        s += k4.x*v4.x + k4.y*v4.y + k4.z*v4.z + k4.w*v4.w;
    }
    float tot = blockReduceSum(s, sh);
    if (t == 0) g_u[r] = INV_B / tot;
}

// per-row: pi = u_r * K[r][:] * v ; lse, rowsum, diag. ce term = lse - pi_rr
__global__ void rowfinal_kernel() {
    __shared__ float sh[4];
    int r = blockIdx.x;
    int t = threadIdx.x;    // 128
    float ur = g_u[r];
    const float4* Krow = (const float4*)(g_K + (size_t)r * BATCH);
    const float4* vv = (const float4*)g_v;
    float se = 0.0f, rs = 0.0f;
    #pragma unroll
    for (int i = 0; i < 8; i++) {
        float4 k4 = Krow[t + 128 * i];
        float4 v4 = vv[t + 128 * i];
        float p0 = ur * k4.x * v4.x;
        float p1 = ur * k4.y * v4.y;
        float p2 = ur * k4.z * v4.z;
        float p3 = ur * k4.w * v4.w;
        se += expf(p0) + expf(p1) + expf(p2) + expf(p3);
        rs += p0 + p1 + p2 + p3;
    }
    float se_t = blockReduceSum(se, sh);
    float rs_t = blockReduceSum(rs, sh);
    if (t == 0) {
        float diag = ur * g_K[(size_t)r * BATCH + r] * g_v[r];
        g_ce[r] = logf(se_t) - diag;
        g_rowsum[r] = rs_t;
    }
}

// combine everything into the scalar loss
__global__ void final_kernel(float* __restrict__ out) {
    __shared__ float sh[8];
    int t = threadIdx.x;   // 256
    float ce = 0.0f, klr = 0.0f, klc = 0.0f;
    for (int i = t; i < BATCH; i += 256) {
        ce += g_ce[i];
        float rs = g_rowsum[i];
        klr += rs * (logf(rs) - INV_B);
        float cs = g_col[i];
        klc += cs * (logf(cs) - INV_B);
    }
    float ce_t  = blockReduceSum(ce,  sh);
    float klr_t = blockReduceSum(klr, sh);
    float klc_t = blockReduceSum(klc, sh);
    if (t == 0)
        out[0] = ce_t * INV_B + REG_W * (klc_t * INV_B + klr_t * INV_B);
}

// ---------------- launcher ----------------
extern "C" void kernel_launch(void* const* d_in, const int* in_sizes, int n_in,
                              void* d_out, int out_size) {
    const float* audio = (const float*)d_in[0];
    const float* text  = (const float*)d_in[1];
    float* out = (float*)d_out;

    init_kernel<<<16, 256>>>();
    normalize_kernel<<<2 * BATCH, 256>>>(audio, text);
    gemm_mma_kernel<<<dim3(BATCH / BN, BATCH / BM), 256>>>();
    expk_kernel<<<16384, 256>>>();

    for (int it = 0; it < NITER; it++) {
        colpart_kernel<false><<<128, 256>>>();
        colreduce_kernel<<<16, 256>>>(0);
        rowdot_kernel<<<BATCH, 128>>>();
    }

    colpart_kernel<true><<<128, 256>>>();
    colreduce_kernel<<<16, 256>>>(1);
    rowfinal_kernel<<<BATCH, 128>>>();
    final_kernel<<<1, 256>>>(out);
}